// round 14
// baseline (speedup 1.0000x reference)
#include <cuda_runtime.h>
#include <cuda_fp16.h>
#include <math.h>
#include <stdint.h>

// ---------------------------------------------------------------------------
// ConvKAN as conv3x3-GEMM over expanded features (silu + 6 cubic B-spline
// bases), fp16 inputs, fp32 accumulation.
//   M = 32768 pixels, N = 128 outputs, K = 9*448 = 4032
// GEMM: mma.sync.m16n8k16 + ldmatrix.x4 (SW128 swizzle) + cp.async.cg,
//   CTA tile 256x128 (low LDS bytes/MAC), 1 CTA/SM, balanced split-K,
//   REGISTER DOUBLE-BUFFERED fragments: LDSM for k-step kk+1 issues before
//   the 32 HMMAs of kk, hiding LDSM latency inside the tensor phase
//   (only 2 warps/SMSP here, so occupancy alone cannot hide it).
// ---------------------------------------------------------------------------

#define B_      8
#define H_      64
#define W_      64
#define CIN     64
#define COUT    128
#define FEAT    7
#define CEXP    (CIN*FEAT)   // 448
#define HP      (H_+2)
#define WP      (W_+2)
#define KTOT    (9*CEXP)     // 4032
#define BKH     64           // halves per K-tile (128B rows)
#define NCH     (CEXP/BKH)   // 7 chunks per tap
#define NIT     (9*NCH)      // 63 K-tiles per output tile
#define NTILE   128          // output tiles (256 pixels x 128 outputs)
#define NCTA    148          // 1 CTA per SM, one wave
#define NU      (NTILE*NIT)  // 8064 work units

__device__ __align__(128) __half g_A[(size_t)B_*HP*WP*CEXP];  // expanded (halo=f(0))
__device__ __align__(128) __half g_Wt[(size_t)COUT*KTOT];     // packed weights [o][k]

__device__ __forceinline__ uint32_t smem_u32(const void* p) {
    uint32_t a;
    asm("{ .reg .u64 t; cvta.to.shared.u64 t, %1; cvt.u32.u64 %0, t; }"
        : "=r"(a) : "l"(p));
    return a;
}
#define CP_ASYNC16(dst, src) \
    asm volatile("cp.async.cg.shared.global [%0], [%1], 16;" :: "r"(dst), "l"(src))
#define CP_COMMIT() asm volatile("cp.async.commit_group;" ::: "memory")
#define CP_WAIT(n)  asm volatile("cp.async.wait_group %0;" :: "n"(n) : "memory")
#define LDSM_X4(r, a) \
    asm volatile("ldmatrix.sync.aligned.m8n8.x4.shared.b16 {%0,%1,%2,%3}, [%4];" \
        : "=r"((r)[0]), "=r"((r)[1]), "=r"((r)[2]), "=r"((r)[3]) : "r"(a))
#define RED_ADD_F32(p, v) \
    asm volatile("red.global.add.f32 [%0], %1;" :: "l"(p), "f"(v) : "memory")

// ---------------------------------------------------------------------------
// Kernel 1 (fused): [0,NEXP) expand x->A; [NEXP,+NWPK) pack W; rest zero out.
// ---------------------------------------------------------------------------
#define NEXP  ((B_*HP*WP)/4)                 // 8712 expand blocks
#define NWPK  ((COUT*KTOT + 255)/256)        // 2016 wpack blocks
#define NZERO ((32768*COUT/4)/256)           // 4096 zero blocks (float4 each)

__global__ __launch_bounds__(256) void prep_kernel(
        const float* __restrict__ x,
        const float* __restrict__ base_w,
        const float* __restrict__ spline_w,
        float* __restrict__ out) {
    if (blockIdx.x >= NEXP + NWPK) {
        int idx = (blockIdx.x - NEXP - NWPK) * 256 + threadIdx.x;
        ((float4*)out)[idx] = make_float4(0.f, 0.f, 0.f, 0.f);
        return;
    }
    if (blockIdx.x >= NEXP) {
        // ---- weight pack: g_Wt[o][k], k = tap*448 + c*7 + t, i = c*9 + tap
        int idx = (blockIdx.x - NEXP) * 256 + threadIdx.x;
        if (idx >= COUT*KTOT) return;
        int o = idx / KTOT;
        int k = idx - o * KTOT;
        int tap = k / CEXP;
        int cc  = k - tap * CEXP;
        int c   = cc / FEAT;
        int t   = cc - c * FEAT;
        int i   = c * 9 + tap;
        float w = (t == 0) ? base_w[(size_t)o * 576 + i]
                           : spline_w[((size_t)o * 576 + i) * 6 + (t - 1)];
        g_Wt[idx] = __float2half_rn(w);
        return;
    }

    __shared__ __half st[4*CEXP];
    int t = threadIdx.x;
    int p = t >> 6, c = t & 63;
    int pix = blockIdx.x * 4 + p;
    int wp  = pix % WP;
    int t1  = pix / WP;
    int hp  = t1 % HP;
    int n   = t1 / HP;

    bool halo = (hp == 0 || hp == HP-1 || wp == 0 || wp == WP-1);
    float v = halo ? 0.0f
                   : x[(((size_t)n * H_ + (hp-1)) * W_ + (wp-1)) * CIN + c];

    float s = v / (1.0f + __expf(-v));

    __half* d = st + p * CEXP + c * FEAT;
    d[0] = __float2half_rn(s);
    d[1] = __half(0.0f); d[2] = __half(0.0f); d[3] = __half(0.0f);
    d[4] = __half(0.0f); d[5] = __half(0.0f); d[6] = __half(0.0f);

    // uniform cubic B-spline: interval j = floor((v+3)*1.5) in [0,8],
    // pieces n0..n3 -> basis slots m = j-3..j, clipped to [0,5].
    float tpos = (v + 3.0f) * 1.5f;
    float fj = floorf(tpos);
    int j = (int)fj;
    if (j >= 0 && j <= 8) {
        float u  = tpos - fj;
        float um = 1.0f - u;
        float u2 = u*u, u3 = u2*u;
        const float k6 = 1.0f/6.0f;
        float n0 = um*um*um*k6;
        float n1 = (3.0f*u3 - 6.0f*u2 + 4.0f)*k6;
        float n2 = (-3.0f*u3 + 3.0f*u2 + 3.0f*u + 1.0f)*k6;
        float n3 = u3*k6;
        int m0 = j - 3;
        if (m0     >= 0 && m0     < 6) d[1 + m0] = __float2half_rn(n0);
        if (m0 + 1 >= 0 && m0 + 1 < 6) d[2 + m0] = __float2half_rn(n1);
        if (m0 + 2 >= 0 && m0 + 2 < 6) d[3 + m0] = __float2half_rn(n2);
        if (m0 + 3 >= 0 && m0 + 3 < 6) d[4 + m0] = __float2half_rn(n3);
    }
    __syncthreads();

    const uint4* s4 = (const uint4*)st;
    uint4* d4 = (uint4*)(g_A + (size_t)blockIdx.x * 4 * CEXP);
    if (t < 224) d4[t] = s4[t];   // 4*448 halves = 224 uint4
}

// ---------------------------------------------------------------------------
// Kernel 2: fp16 HMMA GEMM, BM=256 x BN=128 x BK=64, balanced split-K.
// smem: 3 stages x 48KB (A 32KB @+0, B 16KB @+32K). SW128 swizzle rows.
// 8 warps = 4(m) x 2(n), warp tile 64x64. Register-double-buffered frags.
// Single barrier per K-tile:
//   wait(own tile-kt) -> __syncthreads -> issue kt+2 -> compute kt.
// ---------------------------------------------------------------------------
#define STGB    49152
#define STG(s)  ((s)*STGB)
#define SMEM_TOTAL (3*STGB)   // 144 KB

__global__ __launch_bounds__(256, 1) void convkan_hmma(
        const float* __restrict__ bias, float* __restrict__ out) {
    extern __shared__ char smem[];
    const uint32_t sb = smem_u32(smem);

    const int bid  = blockIdx.x;          // 0..147
    const int tid  = threadIdx.x;
    const int warp = tid >> 5;
    const int lane = tid & 31;
    const int gid  = lane >> 2;
    const int tig  = lane & 3;
    const int wm   = (warp & 3) * 64;     // 4 m-warps
    const int wn   = (warp >> 2) * 64;    // 2 n-warps

    // ---- loader algebra: thread handles 16B unit f = tid&7 of rows
    // r0 + 32*i (A: i=0..7 -> rows 0..255, B: i=0..3 -> rows 0..127).
    const int fA = tid & 7;
    const int r0 = tid >> 3;              // 0..31
    const uint32_t swcol = ((uint32_t)(fA ^ (r0 & 7))) << 4;
    const uint32_t ldstA = sb + (uint32_t)r0 * 128 + swcol;      // + i*4096
    const uint32_t ldstB = ldstA + 32768;                        // + i*4096
    const __half* bG = g_Wt + (size_t)r0 * KTOT + fA * 8;

    // ---- ldmatrix lane constants ----
    const int rA   = (lane & 7) + ((lane >> 3) & 1) * 8;
    const int segA = lane >> 4;
    const uint32_t aXor = (uint32_t)(rA & 7) << 4;
    const int rB   = (lane & 7) + (((lane >> 4) & 1) ? 8 : 0);
    const int segB = (lane >> 3) & 1;
    const uint32_t bXor = (uint32_t)(rB & 7) << 4;

    int u0 = (bid * NU) / NCTA;
    const int u1 = ((bid + 1) * NU) / NCTA;

    while (u0 < u1) {
        const int tile = u0 / NIT;            // 0..127
        const int kt0  = u0 - tile * NIT;
        const int kend = min(u1 - tile * NIT, NIT);
        const int tn_  = tile >> 4;           // batch
        const int th0  = (tile & 15) << 2;    // 4 image rows
        const __half* aT = g_A + (size_t)(tn_ * HP + th0) * WP * CEXP
                         + (size_t)r0 * CEXP + fA * 8;   // row r0 base

        __syncthreads();   // previous segment's stages fully consumed

        float acc[4][8][4];
        #pragma unroll
        for (int mt = 0; mt < 4; mt++)
            #pragma unroll
            for (int nt = 0; nt < 8; nt++)
                #pragma unroll
                for (int q = 0; q < 4; q++) acc[mt][nt][q] = 0.0f;

        // ---- prologue: tiles kt0 (stage0), kt0+1 (stage1) ----
        #pragma unroll 1
        for (int pp = 0; pp < 2; ++pp) {
            int kp = kt0 + pp;
            if (kp < kend) {
                int tap = kp / NCH, ct = kp - tap * NCH;
                int koffA = ((tap / 3) * WP + (tap % 3)) * CEXP + ct * BKH;
                int koffB = tap * CEXP + ct * BKH;
                const uint32_t s0 = STG(pp);
                #pragma unroll
                for (int i = 0; i < 8; i++) {
                    const __half* src = aT + koffA
                        + ((i >> 1) * WP + (i & 1) * 32) * CEXP;
                    CP_ASYNC16(ldstA + s0 + i * 4096, src);
                }
                #pragma unroll
                for (int i = 0; i < 4; i++)
                    CP_ASYNC16(ldstB + s0 + i * 4096,
                               bG + koffB + (size_t)(i * 32) * KTOT);
            }
            CP_COMMIT();
        }

        int stage = 0;
        for (int kt = kt0; kt < kend; ++kt) {
            CP_WAIT(1);        // own group for tile kt complete
            __syncthreads();   // publish all threads' tile-kt data; compute
                               // kt-1 done -> stage (stage+2)%3 reusable

            if (kt + 2 < kend) {
                int kn = kt + 2;
                int tap = kn / NCH, ct = kn - tap * NCH;
                int koffA = ((tap / 3) * WP + (tap % 3)) * CEXP + ct * BKH;
                int koffB = tap * CEXP + ct * BKH;
                const uint32_t ns = STG((stage + 2) % 3);
                #pragma unroll
                for (int i = 0; i < 8; i++) {
                    const __half* src = aT + koffA
                        + ((i >> 1) * WP + (i & 1) * 32) * CEXP;
                    CP_ASYNC16(ldstA + ns + i * 4096, src);
                }
                #pragma unroll
                for (int i = 0; i < 4; i++)
                    CP_ASYNC16(ldstB + ns + i * 4096,
                               bG + koffB + (size_t)(i * 32) * KTOT);
            }
            CP_COMMIT();   // exactly one group per iteration

            const uint32_t Ab = sb + STG(stage);
            const uint32_t Bb = Ab + 32768;

            // ---- register double-buffered fragment pipeline over kk ----
            uint32_t afr[2][4][4];
            uint32_t bfr[2][4][4];

            // load kk=0 fragments into buffer 0
            #pragma unroll
            for (int mt = 0; mt < 4; mt++) {
                uint32_t addr = Ab + (uint32_t)(wm + mt * 16 + rA) * 128
                              + (((uint32_t)(segA * 16)) ^ aXor);
                LDSM_X4(afr[0][mt], addr);
            }
            #pragma unroll
            for (int np = 0; np < 4; np++) {
                uint32_t addr = Bb + (uint32_t)(wn + np * 16 + rB) * 128
                              + (((uint32_t)(segB * 16)) ^ bXor);
                LDSM_X4(bfr[0][np], addr);
            }

            #pragma unroll
            for (int kk = 0; kk < 4; ++kk) {
                const int cur = kk & 1;
                const int nxt = cur ^ 1;
                // prefetch kk+1 fragments (issue before HMMAs -> the 32
                // HMMAs below hide the LDSM latency)
                if (kk < 3) {
                    const uint32_t kb = (uint32_t)((kk + 1) * 32);
                    #pragma unroll
                    for (int mt = 0; mt < 4; mt++) {
                        uint32_t addr = Ab + (uint32_t)(wm + mt * 16 + rA) * 128
                                      + ((kb + segA * 16) ^ aXor);
                        LDSM_X4(afr[nxt][mt], addr);
                    }
                    #pragma unroll
                    for (int np = 0; np < 4; np++) {
                        uint32_t addr = Bb + (uint32_t)(wn + np * 16 + rB) * 128
                                      + ((kb + segB * 16) ^ bXor);
                        LDSM_X4(bfr[nxt][np], addr);
                    }
                }
                #pragma unroll
                for (int np = 0; np < 4; np++)
                    #pragma unroll
                    for (int u = 0; u < 2; u++) {
                        const uint32_t bb0 = bfr[cur][np][u * 2];
                        const uint32_t bb1 = bfr[cur][np][u * 2 + 1];
                        #pragma unroll
                        for (int mt = 0; mt < 4; mt++) {
                            float* d = acc[mt][np * 2 + u];
                            asm volatile(
                                "mma.sync.aligned.m16n8k16.row.col.f32.f16.f16.f32 "
                                "{%0,%1,%2,%3}, {%4,%5,%6,%7}, {%8,%9}, {%0,%1,%2,%3};\n"
                                : "+f"(d[0]), "+f"(d[1]), "+f"(d[2]), "+f"(d[3])
                                : "r"(afr[cur][mt][0]), "r"(afr[cur][mt][1]),
                                  "r"(afr[cur][mt][2]), "r"(afr[cur][mt][3]),
                                  "r"(bb0), "r"(bb1));
                        }
                    }
            }
            stage = (stage + 1) % 3;
        }

        // ---- segment epilogue: red.add partials (bias once per tile) ----
        const float bsc = (kt0 == 0) ? 1.0f : 0.0f;
        #pragma unroll
        for (int nt = 0; nt < 8; nt++) {
            int col = wn + nt * 8 + tig * 2;
            float bx = bias[col] * bsc, by = bias[col + 1] * bsc;
            #pragma unroll
            for (int mt = 0; mt < 4; mt++) {
                int row0 = tile * 256 + wm + mt * 16 + gid;
                float* p0 = out + (size_t)row0 * COUT + col;
                float* p1 = out + (size_t)(row0 + 8) * COUT + col;
                RED_ADD_F32(p0,     acc[mt][nt][0] + bx);
                RED_ADD_F32(p0 + 1, acc[mt][nt][1] + by);
                RED_ADD_F32(p1,     acc[mt][nt][2] + bx);
                RED_ADD_F32(p1 + 1, acc[mt][nt][3] + by);
            }
        }

        u0 = tile * NIT + kend;
    }
}

// ---------------------------------------------------------------------------
extern "C" void kernel_launch(void* const* d_in, const int* in_sizes, int n_in,
                              void* d_out, int out_size) {
    const float* x        = (const float*)d_in[0];
    const float* base_w   = (const float*)d_in[1];
    const float* spline_w = (const float*)d_in[2];
    const float* bias     = (const float*)d_in[3];
    float* out = (float*)d_out;

    prep_kernel<<<NEXP + NWPK + NZERO, 256>>>(x, base_w, spline_w, out);
    cudaFuncSetAttribute(convkan_hmma,
                         cudaFuncAttributeMaxDynamicSharedMemorySize, SMEM_TOTAL);
    convkan_hmma<<<NCTA, 256, SMEM_TOTAL>>>(bias, out);
}

// round 15
// speedup vs baseline: 1.0677x; 1.0677x over previous
#include <cuda_runtime.h>
#include <cuda_fp16.h>
#include <math.h>
#include <stdint.h>

// ---------------------------------------------------------------------------
// ConvKAN as conv3x3-GEMM over expanded features (silu + 6 cubic B-spline
// bases), fp16 inputs, fp32 accumulation.
//   M = 32768 pixels, N = 128 outputs, K = 9*448 = 4032
// GEMM: mma.sync.m16n8k16 + ldmatrix.x4 (SW128 swizzle) + cp.async.cg.
// Pipeline: BARRIER-FREE 3-stage mbarrier producer/consumer ring
//   (full[s]: 256 cp.async-completion arrives; empty[s]: 256 reader arrives).
//   Warps drift instead of converging; pipeline runs continuously across
//   split-K segment boundaries (no drain/refill).
// Balanced split-K: 296 CTAs (2/SM) over 256x63 work units, red.global.add.
// ---------------------------------------------------------------------------

#define B_      8
#define H_      64
#define W_      64
#define CIN     64
#define COUT    128
#define FEAT    7
#define CEXP    (CIN*FEAT)   // 448
#define HP      (H_+2)
#define WP      (W_+2)
#define KTOT    (9*CEXP)     // 4032
#define BKH     64           // halves per K-tile (128B rows)
#define NCH     (CEXP/BKH)   // 7 chunks per tap
#define NIT     (9*NCH)      // 63 K-tiles per output tile
#define NTILE   256          // output tiles (128 pixels x 128 outputs)
#define NCTA    296          // 2 CTAs per SM, one wave
#define NU      (NTILE*NIT)  // 16128 work units

__device__ __align__(128) __half g_A[(size_t)B_*HP*WP*CEXP];  // expanded (halo=f(0))
__device__ __align__(128) __half g_Wt[(size_t)COUT*KTOT];     // packed weights [o][k]

__device__ __forceinline__ uint32_t smem_u32(const void* p) {
    uint32_t a;
    asm("{ .reg .u64 t; cvta.to.shared.u64 t, %1; cvt.u32.u64 %0, t; }"
        : "=r"(a) : "l"(p));
    return a;
}
#define CP_ASYNC16(dst, src) \
    asm volatile("cp.async.cg.shared.global [%0], [%1], 16;" :: "r"(dst), "l"(src))
#define CP_MBAR_ARRIVE(a) \
    asm volatile("cp.async.mbarrier.arrive.noinc.shared.b64 [%0];" :: "r"(a) : "memory")
#define MBAR_INIT(a, c) \
    asm volatile("mbarrier.init.shared.b64 [%0], %1;" :: "r"(a), "r"((uint32_t)(c)) : "memory")
#define MBAR_ARRIVE(a) \
    asm volatile("{.reg .b64 t; mbarrier.arrive.shared.b64 t, [%0];}" :: "r"(a) : "memory")
#define MBAR_WAIT(a, ph) do { \
    uint32_t _m = (a), _p = (ph), _d; \
    asm volatile("{.reg .pred p; mbarrier.try_wait.parity.acquire.cta.shared::cta.b64 p, [%1], %2;" \
                 " selp.b32 %0, 1, 0, p;}" : "=r"(_d) : "r"(_m), "r"(_p) : "memory"); \
    if (!_d) { \
        asm volatile("{.reg .pred P1; WL%=:\n\t" \
            "mbarrier.try_wait.parity.acquire.cta.shared::cta.b64 P1, [%0], %1, 0x989680;\n\t" \
            "@P1 bra.uni WD%=;\n\t bra.uni WL%=;\n\t WD%=:}" \
            :: "r"(_m), "r"(_p) : "memory"); \
    } \
} while (0)
#define LDSM_X4(r, a) \
    asm volatile("ldmatrix.sync.aligned.m8n8.x4.shared.b16 {%0,%1,%2,%3}, [%4];" \
        : "=r"((r)[0]), "=r"((r)[1]), "=r"((r)[2]), "=r"((r)[3]) : "r"(a))
#define RED_ADD_F32(p, v) \
    asm volatile("red.global.add.f32 [%0], %1;" :: "l"(p), "f"(v) : "memory")

// ---------------------------------------------------------------------------
// Kernel 1 (fused): [0,NEXP) expand x->A; [NEXP,+NWPK) pack W; rest zero out.
// ---------------------------------------------------------------------------
#define NEXP  ((B_*HP*WP)/4)                 // 8712 expand blocks
#define NWPK  ((COUT*KTOT + 255)/256)        // 2016 wpack blocks
#define NZERO ((32768*COUT/4)/256)           // 4096 zero blocks (float4 each)

__global__ __launch_bounds__(256) void prep_kernel(
        const float* __restrict__ x,
        const float* __restrict__ base_w,
        const float* __restrict__ spline_w,
        float* __restrict__ out) {
    if (blockIdx.x >= NEXP + NWPK) {
        int idx = (blockIdx.x - NEXP - NWPK) * 256 + threadIdx.x;
        ((float4*)out)[idx] = make_float4(0.f, 0.f, 0.f, 0.f);
        return;
    }
    if (blockIdx.x >= NEXP) {
        // ---- weight pack: g_Wt[o][k], k = tap*448 + c*7 + t, i = c*9 + tap
        int idx = (blockIdx.x - NEXP) * 256 + threadIdx.x;
        if (idx >= COUT*KTOT) return;
        int o = idx / KTOT;
        int k = idx - o * KTOT;
        int tap = k / CEXP;
        int cc  = k - tap * CEXP;
        int c   = cc / FEAT;
        int t   = cc - c * FEAT;
        int i   = c * 9 + tap;
        float w = (t == 0) ? base_w[(size_t)o * 576 + i]
                           : spline_w[((size_t)o * 576 + i) * 6 + (t - 1)];
        g_Wt[idx] = __float2half_rn(w);
        return;
    }

    __shared__ __half st[4*CEXP];
    int t = threadIdx.x;
    int p = t >> 6, c = t & 63;
    int pix = blockIdx.x * 4 + p;
    int wp  = pix % WP;
    int t1  = pix / WP;
    int hp  = t1 % HP;
    int n   = t1 / HP;

    bool halo = (hp == 0 || hp == HP-1 || wp == 0 || wp == WP-1);
    float v = halo ? 0.0f
                   : x[(((size_t)n * H_ + (hp-1)) * W_ + (wp-1)) * CIN + c];

    float s = v / (1.0f + __expf(-v));

    __half* d = st + p * CEXP + c * FEAT;
    d[0] = __float2half_rn(s);
    d[1] = __half(0.0f); d[2] = __half(0.0f); d[3] = __half(0.0f);
    d[4] = __half(0.0f); d[5] = __half(0.0f); d[6] = __half(0.0f);

    // uniform cubic B-spline: interval j = floor((v+3)*1.5) in [0,8],
    // pieces n0..n3 -> basis slots m = j-3..j, clipped to [0,5].
    float tpos = (v + 3.0f) * 1.5f;
    float fj = floorf(tpos);
    int j = (int)fj;
    if (j >= 0 && j <= 8) {
        float u  = tpos - fj;
        float um = 1.0f - u;
        float u2 = u*u, u3 = u2*u;
        const float k6 = 1.0f/6.0f;
        float n0 = um*um*um*k6;
        float n1 = (3.0f*u3 - 6.0f*u2 + 4.0f)*k6;
        float n2 = (-3.0f*u3 + 3.0f*u2 + 3.0f*u + 1.0f)*k6;
        float n3 = u3*k6;
        int m0 = j - 3;
        if (m0     >= 0 && m0     < 6) d[1 + m0] = __float2half_rn(n0);
        if (m0 + 1 >= 0 && m0 + 1 < 6) d[2 + m0] = __float2half_rn(n1);
        if (m0 + 2 >= 0 && m0 + 2 < 6) d[3 + m0] = __float2half_rn(n2);
        if (m0 + 3 >= 0 && m0 + 3 < 6) d[4 + m0] = __float2half_rn(n3);
    }
    __syncthreads();

    const uint4* s4 = (const uint4*)st;
    uint4* d4 = (uint4*)(g_A + (size_t)blockIdx.x * 4 * CEXP);
    if (t < 224) d4[t] = s4[t];   // 4*448 halves = 224 uint4
}

// ---------------------------------------------------------------------------
// Kernel 2: fp16 HMMA GEMM, BM=128 x BN=128 x BK=64, balanced split-K,
// barrier-free 3-stage mbarrier pipeline.
// smem: stage s at s*32KB (A 16KB, B 16KB); mbarriers at +96KB.
// 8 warps = 4(m) x 2(n), warp tile 32x64.
// Per unit ui (uniform control flow for exact arrival counts):
//   if writing ui+2: (wait empty[(ui+2)%3] unless first write) ->
//        8 cp.async -> cp.async.mbarrier.arrive(full)
//   wait full[ui%3] (acquire) -> LDSM+HMMA -> arrive empty[ui%3]
//   flush accumulators inline when tile changes (pipeline keeps flowing).
// ---------------------------------------------------------------------------
#define STGB    32768
#define MB_OFF  (3*STGB)               // 98304
#define SMEM_TOTAL (MB_OFF + 64)       // 98368

__global__ __launch_bounds__(256, 2) void convkan_hmma(
        const float* __restrict__ bias, float* __restrict__ out) {
    extern __shared__ char smem[];
    const uint32_t sb = smem_u32(smem);

    const int bid  = blockIdx.x;          // 0..295
    const int tid  = threadIdx.x;
    const int warp = tid >> 5;
    const int lane = tid & 31;
    const int gid  = lane >> 2;
    const int tig  = lane & 3;
    const int wm   = (warp & 3) * 32;
    const int wn   = (warp >> 2) * 64;

    // mbarrier addresses
    const uint32_t mbF = sb + MB_OFF;       // full[s] = mbF + 8s
    const uint32_t mbE = sb + MB_OFF + 24;  // empty[s] = mbE + 8s

    if (tid == 0) {
        #pragma unroll
        for (int s = 0; s < 3; s++) {
            MBAR_INIT(mbF + 8*s, 256);
            MBAR_INIT(mbE + 8*s, 256);
        }
    }
    __syncthreads();   // one-time init barrier

    // ---- loader constants: 4 16B units per thread (A and B share row/f) ----
    int   aOff[4];
    const __half* bGp[4];
    uint32_t ldst[4];
    #pragma unroll
    for (int i = 0; i < 4; i++) {
        int unit = i * 256 + tid;         // 0..1023
        int row  = unit >> 3;             // 0..127
        int f    = unit & 7;              // 16B unit in 128B row
        int hl   = row >> 6, wl = row & 63;
        aOff[i] = (hl * WP + wl) * CEXP + f * 8;
        bGp[i]  = g_Wt + (size_t)row * KTOT + f * 8;
        ldst[i] = sb + row * 128 + (((uint32_t)f ^ (row & 7)) << 4);
    }

    // ---- ldmatrix lane constants ----
    const int rA   = (lane & 7) + ((lane >> 3) & 1) * 8;
    const int segA = lane >> 4;
    const uint32_t aRow = (uint32_t)(wm + rA) * 128;
    const uint32_t aXor = (uint32_t)(rA & 7) << 4;
    const int rB   = (lane & 7) + (((lane >> 4) & 1) ? 8 : 0);
    const int segB = (lane >> 3) & 1;
    const uint32_t bXor = (uint32_t)(rB & 7) << 4;

    const int u0 = (bid * NU) / NCTA;
    const int u1 = ((bid + 1) * NU) / NCTA;

    // write one unit's tiles into stage (8 cp.async) + completion arrive
    auto write_unit = [&](int u, uint32_t stgoff) {
        int tile = u / NIT;
        int kt   = u - tile * NIT;
        int tap  = kt / NCH;
        int ct   = kt - tap * NCH;
        int kh   = tap / 3, kw = tap - kh * 3;
        const __half* aB = g_A
            + (size_t)((tile >> 5) * HP + ((tile & 31) << 1)) * WP * CEXP;
        int koffA = (kh * WP + kw) * CEXP + ct * BKH;
        int koffB = tap * CEXP + ct * BKH;
        #pragma unroll
        for (int i = 0; i < 4; i++)
            CP_ASYNC16(ldst[i] + stgoff, aB + aOff[i] + koffA);
        #pragma unroll
        for (int i = 0; i < 4; i++)
            CP_ASYNC16(ldst[i] + stgoff + 16384, bGp[i] + koffB);
    };

    float acc[2][8][4];
    #pragma unroll
    for (int mt = 0; mt < 2; mt++)
        #pragma unroll
        for (int nt = 0; nt < 8; nt++)
            #pragma unroll
            for (int q = 0; q < 4; q++) acc[mt][nt][q] = 0.0f;

    // ---- prologue: units u0, u0+1 into stages u0%3, (u0+1)%3 ----
    {
        int s0 = u0 % 3;
        write_unit(u0, (uint32_t)s0 * STGB);
        CP_MBAR_ARRIVE(mbF + 8*s0);
        int s1 = (u0 + 1) % 3;
        write_unit(u0 + 1, (uint32_t)s1 * STGB);
        CP_MBAR_ARRIVE(mbF + 8*s1);
    }

    uint32_t ph_f = 0, ph_e = 0;   // per-stage phase bits
    int curtile = u0 / NIT;
    int ktf     = u0 - curtile * NIT;   // first kt of current tile run

    for (int ui = u0; ui < u1; ++ui) {
        // ---- producer side: write unit ui+2 ----
        if (ui + 2 < u1) {
            int sw = (ui + 2) % 3;
            if (ui != u0) {   // first write to stage (u0+2)%3 needs no wait
                MBAR_WAIT(mbE + 8*sw, (ph_e >> sw) & 1);
                ph_e ^= 1u << sw;
            }
            write_unit(ui + 2, (uint32_t)sw * STGB);
            CP_MBAR_ARRIVE(mbF + 8*sw);
        }

        // ---- consumer side: compute unit ui ----
        int sr = ui % 3;
        MBAR_WAIT(mbF + 8*sr, (ph_f >> sr) & 1);
        ph_f ^= 1u << sr;

        const uint32_t Ab = sb + (uint32_t)sr * STGB;
        const uint32_t Bb = Ab + 16384;

        #pragma unroll
        for (int kk = 0; kk < 4; ++kk) {
            uint32_t afr[2][4];
            #pragma unroll
            for (int mt = 0; mt < 2; mt++) {
                uint32_t addr = Ab + aRow + mt * 2048
                              + (((uint32_t)(kk * 32 + segA * 16)) ^ aXor);
                LDSM_X4(afr[mt], addr);
            }
            uint32_t bfr[4][4];
            #pragma unroll
            for (int np = 0; np < 4; np++) {
                uint32_t addr = Bb + (uint32_t)(wn + np * 16 + rB) * 128
                              + (((uint32_t)(kk * 32 + segB * 16)) ^ bXor);
                LDSM_X4(bfr[np], addr);
            }
            #pragma unroll
            for (int np = 0; np < 4; np++)
                #pragma unroll
                for (int u = 0; u < 2; u++) {
                    const uint32_t bb0 = bfr[np][u * 2];
                    const uint32_t bb1 = bfr[np][u * 2 + 1];
                    #pragma unroll
                    for (int mt = 0; mt < 2; mt++) {
                        float* d = acc[mt][np * 2 + u];
                        asm volatile(
                            "mma.sync.aligned.m16n8k16.row.col.f32.f16.f16.f32 "
                            "{%0,%1,%2,%3}, {%4,%5,%6,%7}, {%8,%9}, {%0,%1,%2,%3};\n"
                            : "+f"(d[0]), "+f"(d[1]), "+f"(d[2]), "+f"(d[3])
                            : "r"(afr[mt][0]), "r"(afr[mt][1]),
                              "r"(afr[mt][2]), "r"(afr[mt][3]),
                              "r"(bb0), "r"(bb1));
                    }
                }
        }
        MBAR_ARRIVE(mbE + 8*sr);   // release: reads of stage sr done

        // ---- inline flush at tile boundary (pipeline keeps flowing) ----
        bool last = (ui + 1 == u1);
        int ntile = last ? -1 : (ui + 1) / NIT;
        if (last || ntile != curtile) {
            const float bsc = (ktf == 0) ? 1.0f : 0.0f;
            #pragma unroll
            for (int nt = 0; nt < 8; nt++) {
                int col = wn + nt * 8 + tig * 2;
                float bx = bias[col] * bsc, by = bias[col + 1] * bsc;
                #pragma unroll
                for (int mt = 0; mt < 2; mt++) {
                    int row0 = curtile * 128 + wm + mt * 16 + gid;
                    float* p0 = out + (size_t)row0 * COUT + col;
                    float* p1 = out + (size_t)(row0 + 8) * COUT + col;
                    RED_ADD_F32(p0,     acc[mt][nt][0] + bx);
                    RED_ADD_F32(p0 + 1, acc[mt][nt][1] + by);
                    RED_ADD_F32(p1,     acc[mt][nt][2] + bx);
                    RED_ADD_F32(p1 + 1, acc[mt][nt][3] + by);
                }
            }
            #pragma unroll
            for (int mt = 0; mt < 2; mt++)
                #pragma unroll
                for (int nt = 0; nt < 8; nt++)
                    #pragma unroll
                    for (int q = 0; q < 4; q++) acc[mt][nt][q] = 0.0f;
            if (!last) {
                curtile = ntile;
                ktf = (ui + 1) - ntile * NIT;
            }
        }
    }
}

// ---------------------------------------------------------------------------
extern "C" void kernel_launch(void* const* d_in, const int* in_sizes, int n_in,
                              void* d_out, int out_size) {
    const float* x        = (const float*)d_in[0];
    const float* base_w   = (const float*)d_in[1];
    const float* spline_w = (const float*)d_in[2];
    const float* bias     = (const float*)d_in[3];
    float* out = (float*)d_out;

    prep_kernel<<<NEXP + NWPK + NZERO, 256>>>(x, base_w, spline_w, out);
    cudaFuncSetAttribute(convkan_hmma,
                         cudaFuncAttributeMaxDynamicSharedMemorySize, SMEM_TOTAL);
    convkan_hmma<<<NCTA, 256, SMEM_TOTAL>>>(bias, out);
}